// round 7
// baseline (speedup 1.0000x reference)
#include <cuda_runtime.h>
#include <mma.h>
#include <cuda_fp16.h>
#include <math.h>
#include <cstdint>

using namespace nvcuda;

#define Nn 50000
#define Ee 500000
#define Tt 8
#define Rr 8
#define NT 391                 // ceil(50000/128) row tiles
#define NP (NT*128)            // padded rows = 50048

// smem (bytes): Ah[128][136]h, Al[128][136]h, Bh[64][136]h, Bl[64][136]h
#define LDA 136
#define LDB 136
#define OFF_AH 0
#define OFF_AL 34816           // 128*136*2
#define OFF_BH 69632
#define OFF_BL 87040           // +64*136*2
#define GEMM_SMEM 104448       // 2 blocks/SM
#define STG_LD 132             // fp32 writeback staging ld (in B region)

// ---------------- device scratch ----------------
__device__ float g_k[(size_t)NP*128];
__device__ float g_q[(size_t)Nn*128];
__device__ float g_v[(size_t)NP*128];
__device__ float g_kA[(size_t)Rr*NP*128];
__device__ float g_vM[(size_t)Rr*NP*128];
__device__ float g_score[Ee];
__device__ float g_agg[(size_t)Nn*128];
__device__ int g_bucket[Nn];
__device__ int g_cnt[Tt];
__device__ int g_off[Tt+1];
__device__ int g_cursor[Tt];
// CSR by dst
__device__ int g_dhist[Nn];
__device__ int g_erow[Nn+1];
__device__ int g_ecur[Nn];
__device__ int g_epk[Ee];      // (et<<16) | src

// ---------------- GEMM machinery (unchanged from R6 winner) ----------------
typedef wmma::fragment<wmma::matrix_a, 16, 16, 16, __half, wmma::row_major> FragA;
typedef wmma::fragment<wmma::matrix_b, 16, 16, 16, __half, wmma::row_major> FragB;
typedef wmma::fragment<wmma::accumulator, 16, 16, 16, float> FragC;

__device__ __forceinline__ void split2h(float x, __half& a, __half& b){
    a = __float2half_rn(x);
    b = __float2half_rn(x - __half2float(a));
}
__device__ __forceinline__ void split_store4(float4 v, __half* d1, __half* d2){
    __half a0,b0,a1,b1,a2,b2,a3,b3;
    split2h(v.x,a0,b0); split2h(v.y,a1,b1); split2h(v.z,a2,b2); split2h(v.w,a3,b3);
    __half2* p1 = reinterpret_cast<__half2*>(d1);
    p1[0] = __halves2half2(a0,a1);
    p1[1] = __halves2half2(a2,a3);
    __half2* p2 = reinterpret_cast<__half2*>(d2);
    p2[0] = __halves2half2(b0,b1);
    p2[1] = __halves2half2(b2,b3);
}

__device__ __forceinline__ void stage_A_gather(char* smem, const float* __restrict__ X,
                                               const int* rows_s, int mc, int tid){
    __half* Ah = reinterpret_cast<__half*>(smem + OFF_AH);
    __half* Al = reinterpret_cast<__half*>(smem + OFF_AL);
    #pragma unroll
    for (int i = 0; i < 16; i++){
        int idx = tid + i*256;
        int m = idx >> 5, c4 = idx & 31;
        float4 v = make_float4(0.f,0.f,0.f,0.f);
        if (m < mc) v = *reinterpret_cast<const float4*>(X + (size_t)rows_s[m]*128 + c4*4);
        split_store4(v, Ah + m*LDA + c4*4, Al + m*LDA + c4*4);
    }
}
__device__ __forceinline__ void stage_A_linear(char* smem, const float* __restrict__ X,
                                               int row0, int tid){
    __half* Ah = reinterpret_cast<__half*>(smem + OFF_AH);
    __half* Al = reinterpret_cast<__half*>(smem + OFF_AL);
    #pragma unroll
    for (int i = 0; i < 16; i++){
        int idx = tid + i*256;
        int m = idx >> 5, c4 = idx & 31;
        float4 v = *reinterpret_cast<const float4*>(X + (size_t)(row0 + m)*128 + c4*4);
        split_store4(v, Ah + m*LDA + c4*4, Al + m*LDA + c4*4);
    }
}
__device__ __forceinline__ void stage_B_split(char* smem, const float* __restrict__ W,
                                              int ch, int tid){
    __half* Bh = reinterpret_cast<__half*>(smem + OFF_BH);
    __half* Bl = reinterpret_cast<__half*>(smem + OFF_BL);
    #pragma unroll
    for (int i = 0; i < 8; i++){
        int idx = tid + i*256;
        int row = idx >> 5, c4 = idx & 31;
        float4 v = *reinterpret_cast<const float4*>(W + (size_t)(ch*64 + row)*128 + c4*4);
        split_store4(v, Bh + row*LDB + c4*4, Bl + row*LDB + c4*4);
    }
}
__device__ __forceinline__ void mma_chunk(const char* smem, FragC cf[8], int wrow0, int ch){
    const __half* Ah = reinterpret_cast<const __half*>(smem + OFF_AH);
    const __half* Al = reinterpret_cast<const __half*>(smem + OFF_AL);
    const __half* Bh = reinterpret_cast<const __half*>(smem + OFF_BH);
    const __half* Bl = reinterpret_cast<const __half*>(smem + OFF_BL);
    #pragma unroll
    for (int kk2 = 0; kk2 < 64; kk2 += 16){
        int kk = ch*64 + kk2;
        FragA ah, al;
        wmma::load_matrix_sync(ah, Ah + wrow0*LDA + kk, LDA);
        wmma::load_matrix_sync(al, Al + wrow0*LDA + kk, LDA);
        #pragma unroll
        for (int nt = 0; nt < 8; nt++){
            FragB bh, bl;
            wmma::load_matrix_sync(bh, Bh + kk2*LDB + nt*16, LDB);
            wmma::load_matrix_sync(bl, Bl + kk2*LDB + nt*16, LDB);
            wmma::mma_sync(cf[nt], ah, bl, cf[nt]);
            wmma::mma_sync(cf[nt], al, bh, cf[nt]);
            wmma::mma_sync(cf[nt], ah, bh, cf[nt]);
        }
    }
}
__device__ __forceinline__ void writeback_gather(char* smem, float* __restrict__ C,
                                                 const int* rows_s, int mc,
                                                 FragC cf[8], int wid, int tid, float gate){
    float* stg = reinterpret_cast<float*>(smem + OFF_BH);
    for (int ph = 0; ph < 2; ph++){
        __syncthreads();
        if ((wid >> 2) == ph){
            int lr0 = (wid & 3) * 16;
            #pragma unroll
            for (int nt = 0; nt < 8; nt++)
                wmma::store_matrix_sync(stg + lr0*STG_LD + nt*16, cf[nt], STG_LD, wmma::mem_row_major);
        }
        __syncthreads();
        #pragma unroll
        for (int i = 0; i < 8; i++){
            int idx = tid + i*256;
            int m = idx >> 5, c4 = idx & 31;
            int gm = ph*64 + m;
            if (gm < mc){
                float4 v = *reinterpret_cast<const float4*>(stg + m*STG_LD + c4*4);
                v.x *= gate; v.y *= gate; v.z *= gate; v.w *= gate;
                *reinterpret_cast<float4*>(C + (size_t)rows_s[gm]*128 + c4*4) = v;
            }
        }
    }
}

// ---------------- init / bucketing / CSR sort ----------------
__global__ void init_kernel(){
    int i = blockIdx.x * 256 + threadIdx.x;
    if (i < Nn) g_dhist[i] = 0;
    if (i < Tt) g_cnt[i] = 0;
}
__global__ void hist_kernel(const int* __restrict__ nt){
    int n = blockIdx.x * 256 + threadIdx.x;
    if (n < Nn) atomicAdd(&g_cnt[nt[n]], 1);
}
__global__ void prefix_kernel(){
    if (threadIdx.x == 0){
        int s = 0;
        for (int t = 0; t < Tt; t++){
            g_off[t] = s; g_cursor[t] = s; s += g_cnt[t];
        }
        g_off[Tt] = s;
    }
}
__global__ void scatter_kernel(const int* __restrict__ nt){
    int n = blockIdx.x * 256 + threadIdx.x;
    if (n < Nn){
        int p = atomicAdd(&g_cursor[nt[n]], 1);
        g_bucket[p] = n;
    }
}
__global__ void dhist_kernel(const int* __restrict__ dst){
    int e = blockIdx.x * 256 + threadIdx.x;
    if (e < Ee) atomicAdd(&g_dhist[dst[e]], 1);
}
// 1-block scan of g_dhist -> g_erow / g_ecur
__global__ void __launch_bounds__(1024) scan_kernel(){
    __shared__ int parts[1024];
    int t = threadIdx.x;
    const int CH = (Nn + 1023) / 1024;   // 49
    int lo = t * CH, hi = min(lo + CH, Nn);
    int s = 0;
    for (int j = lo; j < hi; j++) s += g_dhist[j];
    parts[t] = s;
    __syncthreads();
    for (int off = 1; off < 1024; off <<= 1){
        int v = (t >= off) ? parts[t - off] : 0;
        __syncthreads();
        parts[t] += v;
        __syncthreads();
    }
    int run = (t > 0) ? parts[t-1] : 0;
    for (int j = lo; j < hi; j++){
        g_erow[j] = run; g_ecur[j] = run;
        run += g_dhist[j];
    }
    if (t == 1023) g_erow[Nn] = run;
}
__global__ void escatter_kernel(const int* __restrict__ src, const int* __restrict__ dst,
                                const int* __restrict__ et){
    int e = blockIdx.x * 256 + threadIdx.x;
    if (e < Ee){
        int pos = atomicAdd(&g_ecur[dst[e]], 1);
        g_epk[pos] = src[e] | (et[e] << 16);
    }
}
__global__ void zeropad_kernel(float* __restrict__ k, float* __restrict__ v){
    int i = blockIdx.x * 256 + threadIdx.x;
    if (i < (NP - Nn)*128){
        k[(size_t)Nn*128 + i] = 0.f;
        v[(size_t)Nn*128 + i] = 0.f;
    }
}

// ---------------- K1: per-type fused k/q/v projection ----------------
__global__ void __launch_bounds__(256, 2) proj_kqv_kernel(
    const float* __restrict__ h,
    const float* __restrict__ kw, const float* __restrict__ qw, const float* __restrict__ vw,
    float* __restrict__ ok, float* __restrict__ oq, float* __restrict__ ov)
{
    extern __shared__ char smem[];
    __shared__ int rows_s[128];

    int tid = threadIdx.x, wid = tid >> 5;
    int t = blockIdx.y;
    int base = g_off[t];
    int cnt = g_off[t+1] - base;
    int tb = blockIdx.x * 128;
    if (tb >= cnt) return;
    int mc = min(128, cnt - tb);

    if (tid < 128) rows_s[tid] = (tid < mc) ? g_bucket[base + tb + tid] : 0;
    __syncthreads();
    stage_A_gather(smem, h, rows_s, mc, tid);

    const float* Wsrc[3] = { kw + t*16384, qw + t*16384, vw + t*16384 };
    float* Cd[3] = { ok, oq, ov };
    int wrow0 = wid * 16;

    for (int w = 0; w < 3; w++){
        FragC cf[8];
        #pragma unroll
        for (int nt = 0; nt < 8; nt++) wmma::fill_fragment(cf[nt], 0.f);

        for (int ch = 0; ch < 2; ch++){
            __syncthreads();
            stage_B_split(smem, Wsrc[w], ch, tid);
            __syncthreads();
            mma_chunk(smem, cf, wrow0, ch);
        }
        writeback_gather(smem, Cd[w], rows_s, mc, cf, wid, tid, 1.0f);
        __syncthreads();
    }
}

// ---------------- K2: per-relation dense GEMM ----------------
__global__ void __launch_bounds__(256, 2) relproj_kernel(
    const float* __restrict__ Xk, const float* __restrict__ Xv,
    const float* __restrict__ att, const float* __restrict__ msg,
    float* __restrict__ CkA, float* __restrict__ CvM)
{
    extern __shared__ char smem[];
    int tid = threadIdx.x, wid = tid >> 5;
    int tile = blockIdx.x, r = blockIdx.y, z = blockIdx.z;
    const float* X = z ? Xv : Xk;
    const float* W = (z ? msg : att) + (size_t)r*16384;
    float* C = (z ? CvM : CkA) + (size_t)r*NP*128;
    int row0 = tile * 128;
    int wrow0 = wid * 16;

    stage_A_linear(smem, X, row0, tid);

    FragC cf[8];
    #pragma unroll
    for (int nt = 0; nt < 8; nt++) wmma::fill_fragment(cf[nt], 0.f);

    for (int ch = 0; ch < 2; ch++){
        __syncthreads();
        stage_B_split(smem, W, ch, tid);
        __syncthreads();
        mma_chunk(smem, cf, wrow0, ch);
    }

    float* Crow = C + (size_t)(row0 + wrow0)*128;
    #pragma unroll
    for (int nt = 0; nt < 8; nt++)
        wmma::store_matrix_sync(Crow + nt*16, cf[nt], 128, wmma::mem_row_major);
}

// ---------------- K3: fused per-dst edge kernel (warp per dst) ----------------
// pass 1: scores + online softmax (lane r owns running max/denom for relation r)
// pass 2: alpha-weighted vM aggregation, single store to agg[dst]
__global__ void __launch_bounds__(256) edge_fused_kernel(
    const float* __restrict__ kA, const float* __restrict__ vM,
    const float* __restrict__ q, const float* __restrict__ pri,
    float* __restrict__ score, float* __restrict__ agg)
{
    int w = (blockIdx.x * blockDim.x + threadIdx.x) >> 5;   // dst node
    int lane = threadIdx.x & 31;
    if (w >= Nn) return;

    float4 qv = *reinterpret_cast<const float4*>(q + (size_t)w*128 + lane*4);
    int e0 = g_erow[w], e1 = g_erow[w+1];

    float pr[8];
    #pragma unroll
    for (int r = 0; r < 8; r++) pr[r] = pri[r];

    float mxl = -1e30f, dnl = 0.f;     // lane<8: running max/denom for relation==lane

    for (int e = e0; e < e1; e++){
        int p = g_epk[e];
        int r = p >> 16, s = p & 0xffff;
        float4 x = reinterpret_cast<const float4*>(kA + ((size_t)r*NP + s)*128)[lane];
        float acc = x.x*qv.x + x.y*qv.y + x.z*qv.z + x.w*qv.w;
        #pragma unroll
        for (int o = 16; o; o >>= 1) acc += __shfl_xor_sync(0xffffffffu, acc, o);
        float sc = acc * pr[r] * 0.08838834764831845f;   // 1/sqrt(128)
        if (lane == 0) score[e] = sc;
        if (lane == r){
            if (sc > mxl){ dnl = dnl * __expf(mxl - sc) + 1.f; mxl = sc; }
            else dnl += __expf(sc - mxl);
        }
    }

    float4 acc4 = make_float4(0.f, 0.f, 0.f, 0.f);
    for (int e = e0; e < e1; e++){
        int p = g_epk[e];
        int r = p >> 16, s = p & 0xffff;
        float sc = score[e];
        float m = __shfl_sync(0xffffffffu, mxl, r);
        float d = __shfl_sync(0xffffffffu, dnl, r);
        float alpha = __expf(sc - m) / d;
        float4 v = reinterpret_cast<const float4*>(vM + ((size_t)r*NP + s)*128)[lane];
        acc4.x += alpha * v.x;
        acc4.y += alpha * v.y;
        acc4.z += alpha * v.z;
        acc4.w += alpha * v.w;
    }
    *reinterpret_cast<float4*>(agg + (size_t)w*128 + lane*4) = acc4;
}

// ---------------- K4: per-type output transform ----------------
__global__ void __launch_bounds__(256, 2) out_kernel(
    const float* __restrict__ agg, const float* __restrict__ aw,
    const float* __restrict__ skip, float* __restrict__ out)
{
    extern __shared__ char smem[];
    __shared__ int rows_s[128];

    int tid = threadIdx.x, wid = tid >> 5;
    int t = blockIdx.y;
    int base = g_off[t];
    int cnt = g_off[t+1] - base;
    int tb = blockIdx.x * 128;
    if (tb >= cnt) return;
    int mc = min(128, cnt - tb);

    if (tid < 128) rows_s[tid] = (tid < mc) ? g_bucket[base + tb + tid] : 0;
    __syncthreads();
    stage_A_gather(smem, agg, rows_s, mc, tid);

    FragC cf[8];
    #pragma unroll
    for (int nt = 0; nt < 8; nt++) wmma::fill_fragment(cf[nt], 0.f);

    int wrow0 = wid * 16;
    const float* W = aw + (size_t)t*16384;
    for (int ch = 0; ch < 2; ch++){
        __syncthreads();
        stage_B_split(smem, W, ch, tid);
        __syncthreads();
        mma_chunk(smem, cf, wrow0, ch);
    }

    float gate = 1.f / (1.f + __expf(-skip[t]));
    writeback_gather(smem, out, rows_s, mc, cf, wid, tid, gate);
}

// ---------------- launch ----------------
extern "C" void kernel_launch(void* const* d_in, const int* in_sizes, int n_in,
                              void* d_out, int out_size)
{
    const float* h     = (const float*)d_in[0];
    const int*   adj   = (const int*)d_in[1];
    const int*   etype = (const int*)d_in[2];
    const int*   ntype = (const int*)d_in[3];
    const float* kw    = (const float*)d_in[6];
    const float* qw    = (const float*)d_in[7];
    const float* vw    = (const float*)d_in[8];
    const float* aw    = (const float*)d_in[9];
    const float* pri   = (const float*)d_in[10];
    const float* att   = (const float*)d_in[11];
    const float* msg   = (const float*)d_in[12];
    const float* skip  = (const float*)d_in[13];
    const int* src = adj;
    const int* dst = adj + Ee;
    float* out = (float*)d_out;

    cudaFuncSetAttribute(proj_kqv_kernel, cudaFuncAttributeMaxDynamicSharedMemorySize, GEMM_SMEM);
    cudaFuncSetAttribute(relproj_kernel,  cudaFuncAttributeMaxDynamicSharedMemorySize, GEMM_SMEM);
    cudaFuncSetAttribute(out_kernel,      cudaFuncAttributeMaxDynamicSharedMemorySize, GEMM_SMEM);

    void *pk, *pq, *pv, *pkA, *pvM, *pscore, *pagg;
    cudaGetSymbolAddress(&pk, g_k);
    cudaGetSymbolAddress(&pq, g_q);
    cudaGetSymbolAddress(&pv, g_v);
    cudaGetSymbolAddress(&pkA, g_kA);
    cudaGetSymbolAddress(&pvM, g_vM);
    cudaGetSymbolAddress(&pscore, g_score);
    cudaGetSymbolAddress(&pagg, g_agg);

    // init + bucketing + CSR sort by dst
    init_kernel<<<(Nn + 255)/256, 256>>>();
    hist_kernel<<<(Nn + 255)/256, 256>>>(ntype);
    dhist_kernel<<<(Ee + 255)/256, 256>>>(dst);
    prefix_kernel<<<1, 32>>>();
    scan_kernel<<<1, 1024>>>();
    scatter_kernel<<<(Nn + 255)/256, 256>>>(ntype);
    escatter_kernel<<<(Ee + 255)/256, 256>>>(src, dst, etype);
    zeropad_kernel<<<((NP - Nn)*128 + 255)/256, 256>>>((float*)pk, (float*)pv);

    dim3 gT((Nn + 127)/128, Tt);
    proj_kqv_kernel<<<gT, 256, GEMM_SMEM>>>(h, kw, qw, vw,
                                            (float*)pk, (float*)pq, (float*)pv);

    dim3 gR(NT, Rr, 2);
    relproj_kernel<<<gR, 256, GEMM_SMEM>>>((const float*)pk, (const float*)pv,
                                           att, msg, (float*)pkA, (float*)pvM);

    edge_fused_kernel<<<(Nn*32 + 255)/256, 256>>>((const float*)pkA, (const float*)pvM,
                                                  (const float*)pq, pri,
                                                  (float*)pscore, (float*)pagg);

    out_kernel<<<gT, 256, GEMM_SMEM>>>((const float*)pagg, aw, skip, out);
}